// round 9
// baseline (speedup 1.0000x reference)
#include <cuda_runtime.h>
#include <cstdint>

#define Bc   8
#define CCc  512
#define Kc   64
#define Vc   256
#define Tc   1024
#define KSc  23
#define EPSc 1e-5f
#define BKV  (Bc * Kc * Vc)
#define NSPLIT 8

typedef unsigned long long u64t;

#define PACK2(d, v)  asm("mov.b64 %0, {%1, %1};" : "=l"(d) : "f"(v))
#define FMA2(d, a, b) asm("fma.rn.f32x2 %0, %1, %2, %0;" : "+l"(d) : "l"(a), "l"(b))
#define UNPACK2(lo, hi, in) asm("mov.b64 {%0, %1}, %2;" : "=f"(lo), "=f"(hi) : "l"(in))

// ---------------- scratch (device globals) ----------------
__device__ float g_Q[Bc * Kc * Tc];          // raw queries
__device__ float g_K[Bc * Kc * Tc];          // keys -> softmaxed in place
__device__ float g_V[Bc * Vc * Tc];          // raw values
__device__ float g_CLp[NSPLIT * BKV];        // split-T partials of content lambda
__device__ float g_CL[BKV];                  // content lambda (BN(V) folded in)
__device__ float g_qpos[Bc * Tc * KSc];      // qn @ pos_w
__device__ float g_qb[Bc * Tc];              // qn @ pos_b
__device__ float g_qsc[Kc], g_qof[Kc];       // BN(Q) affine
__device__ float g_vsc[Vc], g_vof[Vc];       // BN(V) affine

// ---------------- fused Q/K/V projection (f32x2, pre-duplicated W tile) ------
// C[b][m][t] = sum_c W[m][c]*X[b][c][t] + bias[m]
// 128 threads, BM=64, BN=128, BK=16; per-thread 8m x 4 t-pairs.
__global__ void proj_all(const float* __restrict__ x, const float* __restrict__ ctx,
                         const float* __restrict__ Wq, const float* __restrict__ bq,
                         const float* __restrict__ Wk, const float* __restrict__ bk,
                         const float* __restrict__ Wv, const float* __restrict__ bv,
                         float* __restrict__ Qd, float* __restrict__ Kd,
                         float* __restrict__ Vd)
{
    const int z = blockIdx.z;
    const float *W, *Xb, *bias;
    float* C;
    int b, m0;
    if (z < 8)        { b = z;      m0 = 0;            W = Wq; bias = bq; Xb = x;   C = Qd + (size_t)b * Kc * Tc; }
    else if (z < 16)  { b = z - 8;  m0 = 0;            W = Wk; bias = bk; Xb = ctx; C = Kd + (size_t)b * Kc * Tc; }
    else { int zz = z - 16; b = zz >> 2; m0 = (zz & 3) * 64; W = Wv; bias = bv; Xb = ctx; C = Vd + (size_t)b * Vc * Tc; }
    const float* X = Xb + (size_t)b * CCc * Tc;
    const int n0 = blockIdx.x * 128;

    __shared__ u64t  Wd[16][68];    // duplicated W: Wd[kk][m] = {w, w}
    __shared__ float Xs[16][128];

    const int tid = threadIdx.x;       // 128
    const int tr = tid >> 4;           // 0..7
    const int tc = tid & 15;           // 0..15

    u64t acc[8][4];
#pragma unroll
    for (int i = 0; i < 8; i++)
#pragma unroll
        for (int q = 0; q < 4; q++) acc[i][q] = 0ULL;

    for (int c0 = 0; c0 < CCc; c0 += 16) {
        // W tile transposed + duplicated: Wd[kk][mm] = dup(W[m0+mm][c0+kk])
#pragma unroll
        for (int f = tid; f < 256; f += 128) {
            int mm = f >> 2, c4 = f & 3;
            float4 w = *reinterpret_cast<const float4*>(&W[(size_t)(m0 + mm) * CCc + c0 + c4 * 4]);
            u64t d0, d1, d2, d3;
            PACK2(d0, w.x); PACK2(d1, w.y); PACK2(d2, w.z); PACK2(d3, w.w);
            Wd[c4 * 4 + 0][mm] = d0;
            Wd[c4 * 4 + 1][mm] = d1;
            Wd[c4 * 4 + 2][mm] = d2;
            Wd[c4 * 4 + 3][mm] = d3;
        }
        // X tile: Xs[kk][nn] = X[c0+kk][n0+nn]
#pragma unroll
        for (int f = tid; f < 512; f += 128) {
            int kk = f >> 5, n4 = f & 31;
            *reinterpret_cast<float4*>(&Xs[kk][n4 * 4]) =
                *reinterpret_cast<const float4*>(&X[(size_t)(c0 + kk) * Tc + n0 + n4 * 4]);
        }
        __syncthreads();
#pragma unroll
        for (int kk = 0; kk < 16; kk++) {
            const u64t* xp = reinterpret_cast<const u64t*>(&Xs[kk][tc * 8]);
            u64t xv[4] = {xp[0], xp[1], xp[2], xp[3]};
            const u64t* wp = &Wd[kk][tr * 8];
            ulonglong2 w0 = *reinterpret_cast<const ulonglong2*>(wp);
            ulonglong2 w1 = *reinterpret_cast<const ulonglong2*>(wp + 2);
            ulonglong2 w2 = *reinterpret_cast<const ulonglong2*>(wp + 4);
            ulonglong2 w3 = *reinterpret_cast<const ulonglong2*>(wp + 6);
            u64t av[8] = {w0.x, w0.y, w1.x, w1.y, w2.x, w2.y, w3.x, w3.y};
#pragma unroll
            for (int i = 0; i < 8; i++)
#pragma unroll
                for (int q = 0; q < 4; q++) FMA2(acc[i][q], av[i], xv[q]);
        }
        __syncthreads();
    }
#pragma unroll
    for (int i = 0; i < 8; i++) {
        int m = m0 + tr * 8 + i;
        float bi = bias[m];
        float* cr = C + (size_t)m * Tc + n0 + tc * 8;
        float o[8];
#pragma unroll
        for (int q = 0; q < 4; q++) UNPACK2(o[2 * q], o[2 * q + 1], acc[i][q]);
        float4 o0 = {o[0] + bi, o[1] + bi, o[2] + bi, o[3] + bi};
        float4 o1 = {o[4] + bi, o[5] + bi, o[6] + bi, o[7] + bi};
        *reinterpret_cast<float4*>(cr)     = o0;
        *reinterpret_cast<float4*>(cr + 4) = o1;
    }
}

// ---------------- fused normalize: softmax(K) in place + BN stats for Q,V ----
__global__ void normalize(float* __restrict__ Kd, const float* __restrict__ Qd,
                          const float* __restrict__ Vd,
                          const float* __restrict__ gq, const float* __restrict__ bq,
                          const float* __restrict__ gv, const float* __restrict__ bv,
                          float* __restrict__ qsc, float* __restrict__ qof,
                          float* __restrict__ vsc, float* __restrict__ vof)
{
    const int tid = threadIdx.x;
    __shared__ float rs[256], rq[256];

    if (blockIdx.x < 512) {
        float* r = Kd + (size_t)blockIdx.x * Tc;
        float v[4];
        float m = -1e30f;
#pragma unroll
        for (int j = 0; j < 4; j++) { v[j] = r[tid + j * 256]; m = fmaxf(m, v[j]); }
        rs[tid] = m; __syncthreads();
        for (int s = 128; s > 0; s >>= 1) {
            if (tid < s) rs[tid] = fmaxf(rs[tid], rs[tid + s]);
            __syncthreads();
        }
        m = rs[0]; __syncthreads();
        float sum = 0.f;
#pragma unroll
        for (int j = 0; j < 4; j++) { v[j] = expf(v[j] - m); sum += v[j]; }
        rs[tid] = sum; __syncthreads();
        for (int s = 128; s > 0; s >>= 1) {
            if (tid < s) rs[tid] += rs[tid + s];
            __syncthreads();
        }
        float inv = 1.f / rs[0];
#pragma unroll
        for (int j = 0; j < 4; j++) r[tid + j * 256] = v[j] * inv;
        return;
    }

    const float* data;
    const float *gamma, *beta;
    float *osc, *oof;
    int c, C;
    if (blockIdx.x < 576) { c = blockIdx.x - 512; C = Kc; data = Qd; gamma = gq; beta = bq; osc = qsc; oof = qof; }
    else                  { c = blockIdx.x - 576; C = Vc; data = Vd; gamma = gv; beta = bv; osc = vsc; oof = vof; }

    float s = 0.f, sq = 0.f;
    for (int i = tid; i < Bc * Tc; i += 256) {
        int b = i >> 10, t = i & 1023;
        float z = data[((size_t)b * C + c) * Tc + t];
        s += z; sq += z * z;
    }
    rs[tid] = s; rq[tid] = sq; __syncthreads();
    for (int st = 128; st > 0; st >>= 1) {
        if (tid < st) { rs[tid] += rs[tid + st]; rq[tid] += rq[tid + st]; }
        __syncthreads();
    }
    if (tid == 0) {
        const float invN = 1.f / (Bc * Tc);
        float mean = rs[0] * invN;
        float var  = rq[0] * invN - mean * mean;
        float g  = gamma[c] * rsqrtf(var + EPSc);
        osc[c] = g;
        oof[c] = beta[c] - mean * g;
    }
}

// ---------------- mid kernel: cl_part (blocks 0..255) + qpos (blocks 256..383)
// cl_part: CLp[ts][b][k][v] = sum_{t in 128-chunk ts} K̂[b][k][t]*Vraw[b][v][t]
// qpos:    qpos[b][t][s] = sum_k Qn[b][k][t]*pos_w[k][s];  qb = Qn . pos_b
__global__ void __launch_bounds__(256, 4)
mid_kernel(const float* __restrict__ Kn, const float* __restrict__ Vr,
           float* __restrict__ CLp,
           const float* __restrict__ Qr, const float* __restrict__ pos_w,
           const float* __restrict__ pos_b,
           const float* __restrict__ qsc, const float* __restrict__ qof,
           float* __restrict__ qpos, float* __restrict__ qb)
{
    __shared__ __align__(16) char smembuf[26 * 1024];
    const int tid = threadIdx.x;   // 256

    if (blockIdx.x < 256) {
        // ---- content lambda partial over a 128-wide T chunk ----
        const int xid = blockIdx.x;
        const int v0 = (xid & 3) * 64;
        const int b  = (xid >> 2) & 7;
        const int ts = xid >> 5;         // 0..7
        const float* Ab = Kn + (size_t)b * Kc * Tc;
        const float* Vb = Vr + (size_t)b * Vc * Tc;

        u64t*  As = reinterpret_cast<u64t*>(smembuf);            // [32][68] dup K^T: [tt][k]
        float* Bs = reinterpret_cast<float*>(smembuf + 32 * 68 * 8);  // [32][66] V^T: [tt][v]

        const int tr = tid >> 4;         // k-group of 4
        const int tc = tid & 15;         // v-group of 4 (2 pairs)

        u64t acc[4][2];
#pragma unroll
        for (int i = 0; i < 4; i++) { acc[i][0] = 0ULL; acc[i][1] = 0ULL; }

        for (int t0 = ts * 128; t0 < ts * 128 + 128; t0 += 32) {
#pragma unroll
            for (int i = tid; i < 64 * 32; i += 256) {
                int r = i >> 5, tt = i & 31;
                float kv = Ab[(size_t)r * Tc + t0 + tt];
                u64t d; PACK2(d, kv);
                As[tt * 68 + r] = d;
                Bs[tt * 66 + r] = Vb[(size_t)(v0 + r) * Tc + t0 + tt];
            }
            __syncthreads();
#pragma unroll
            for (int tt = 0; tt < 32; tt++) {
                const u64t* ar = &As[tt * 68 + tr * 4];
                ulonglong2 a01 = *reinterpret_cast<const ulonglong2*>(ar);
                ulonglong2 a23 = *reinterpret_cast<const ulonglong2*>(ar + 2);
                const u64t* br = reinterpret_cast<const u64t*>(&Bs[tt * 66 + tc * 4]);
                u64t b0 = br[0], b1 = br[1];
                u64t a2[4] = {a01.x, a01.y, a23.x, a23.y};
#pragma unroll
                for (int i = 0; i < 4; i++) {
                    FMA2(acc[i][0], a2[i], b0);
                    FMA2(acc[i][1], a2[i], b1);
                }
            }
            __syncthreads();
        }
        float* Cb = CLp + (size_t)ts * BKV + (size_t)b * Kc * Vc;
#pragma unroll
        for (int i = 0; i < 4; i++) {
            float o[4];
            UNPACK2(o[0], o[1], acc[i][0]);
            UNPACK2(o[2], o[3], acc[i][1]);
            *reinterpret_cast<float4*>(&Cb[(size_t)(tr * 4 + i) * Vc + v0 + tc * 4]) =
                make_float4(o[0], o[1], o[2], o[3]);
        }
    } else {
        // ---- qpos tile ----
        const int idx = blockIdx.x - 256;
        const int t0 = (idx & 15) * 64;
        const int b  = idx >> 4;

        float* smem = reinterpret_cast<float*>(smembuf);
        float* Qs  = smem;                      // [64][65]
        float* pws = smem + 64 * 65;            // [64][24]
        float* cs  = smem + 64 * 65 + 64 * 24;  // [24]

        for (int i = tid; i < 64 * 64; i += 256) {
            int k = i >> 6, t = i & 63;
            Qs[k * 65 + t] = Qr[((size_t)b * Kc + k) * Tc + t0 + t];
        }
        for (int i = tid; i < Kc * KSc; i += 256) {
            int k = i / KSc, s = i % KSc;
            pws[k * 24 + s] = qsc[k] * pos_w[k * KSc + s];
        }
        if (tid < Kc) pws[tid * 24 + 23] = qsc[tid] * pos_b[tid];
        if (tid < 24) {
            float c = 0.f;
            if (tid < 23) {
                for (int k = 0; k < Kc; k++) c += qof[k] * pos_w[k * KSc + tid];
            } else {
                for (int k = 0; k < Kc; k++) c += qof[k] * pos_b[k];
            }
            cs[tid] = c;
        }
        __syncthreads();

        const int t  = tid & 63;
        const int sg = tid >> 6;

        float acc[6];
#pragma unroll
        for (int j = 0; j < 6; j++) acc[j] = cs[sg * 6 + j];

#pragma unroll 8
        for (int k = 0; k < Kc; k++) {
            float q = Qs[k * 65 + t];
#pragma unroll
            for (int j = 0; j < 6; j++) acc[j] += q * pws[k * 24 + sg * 6 + j];
        }
#pragma unroll
        for (int j = 0; j < 6; j++) {
            int slot = sg * 6 + j;
            if (slot < 23) qpos[((size_t)b * Tc + t0 + t) * KSc + slot] = acc[j];
            else           qb[(size_t)b * Tc + t0 + t] = acc[j];
        }
    }
}

// CL = vsc[v]*(sum of 8 partials) + vof[v]
__global__ void cl_reduce(const float* __restrict__ CLp, float* __restrict__ CL,
                          const float* __restrict__ vsc, const float* __restrict__ vof)
{
    int i = blockIdx.x * 256 + threadIdx.x;
    int v = i & (Vc - 1);
    float s = 0.f;
#pragma unroll
    for (int p = 0; p < NSPLIT; p++) s += CLp[i + (size_t)p * BKV];
    CL[i] = s * vsc[v] + vof[v];
}

// ---------------- fused output (content part in f32x2) ----------------
__global__ void out_kernel(const float* __restrict__ Qr, const float* __restrict__ CL,
                           const float* __restrict__ Vr, const float* __restrict__ qpos,
                           const float* __restrict__ qb,
                           const float* __restrict__ qsc, const float* __restrict__ qof,
                           const float* __restrict__ vsc, const float* __restrict__ vof,
                           float* __restrict__ out)
{
    const int b  = blockIdx.z;
    const int v0 = blockIdx.y * 32;
    const int t0 = blockIdx.x * 64;
    const int tid = threadIdx.x;
    const int tl = tid & 63;
    const int vlane = tid >> 6;

    __shared__ float Qs[64][64];
    __shared__ float cls[64][32];
    __shared__ float qps[64][25];
    __shared__ float Vs[32][86];
    __shared__ float qsS[64], qoS[64], vsS[32], voS[32];

    if (tid < 64) { qsS[tid] = qsc[tid]; qoS[tid] = qof[tid]; }
    else if (tid < 96)  { vsS[tid - 64] = vsc[v0 + tid - 64]; }
    else if (tid < 128) { voS[tid - 96] = vof[v0 + tid - 96]; }
    __syncthreads();

#pragma unroll 4
    for (int i = tid; i < 64 * 64; i += 256) {
        int k = i >> 6, t = i & 63;
        Qs[k][t] = Qr[((size_t)b * Kc + k) * Tc + t0 + t] * qsS[k] + qoS[k];
    }
#pragma unroll 2
    for (int i = tid; i < 64 * 32; i += 256) {
        int k = i >> 5, vv = i & 31;
        cls[k][vv] = CL[((size_t)b * Kc + k) * Vc + v0 + vv];
    }
    for (int i = tid; i < 64 * KSc; i += 256) {
        int t = i / KSc, s = i % KSc;
        qps[t][s] = qpos[((size_t)b * Tc + t0 + t) * KSc + s];
    }
    if (tid < 64) qps[tid][23] = qb[b * Tc + t0 + tid];
    for (int i = tid; i < 32 * 86; i += 256) {
        int vv = i / 86, idx = i % 86;
        int tg = t0 - 11 + idx;
        Vs[vv][idx] = (tg >= 0 && tg < Tc)
                          ? Vr[((size_t)b * Vc + v0 + vv) * Tc + tg] * vsS[vv] + voS[vv]
                          : 0.f;
    }
    __syncthreads();

    u64t accp[4];
#pragma unroll
    for (int q = 0; q < 4; q++) accp[q] = 0ULL;

#pragma unroll
    for (int k = 0; k < Kc; k++) {
        u64t qv;
        PACK2(qv, Qs[k][tl]);
        const u64t* cp = reinterpret_cast<const u64t*>(&cls[k][vlane * 8]);
#pragma unroll
        for (int q = 0; q < 4; q++) FMA2(accp[q], qv, cp[q]);
    }

    float acc[8];
#pragma unroll
    for (int q = 0; q < 4; q++) UNPACK2(acc[2 * q], acc[2 * q + 1], accp[q]);

#pragma unroll
    for (int s = 0; s < KSc; s++) {
        float qp = qps[tl][s];
#pragma unroll
        for (int j = 0; j < 8; j++) acc[j] += qp * Vs[vlane * 8 + j][tl + s];
    }
    float qbv = qps[tl][23];
#pragma unroll
    for (int j = 0; j < 8; j++)
        out[((size_t)b * Vc + v0 + vlane * 8 + j) * Tc + t0 + tl] = acc[j] + qbv;
}

// ---------------- launch ----------------
extern "C" void kernel_launch(void* const* d_in, const int* in_sizes, int n_in,
                              void* d_out, int out_size)
{
    const float* x       = (const float*)d_in[0];
    const float* context = (const float*)d_in[1];
    const float* Wq      = (const float*)d_in[2];
    const float* bq      = (const float*)d_in[3];
    const float* Wk      = (const float*)d_in[4];
    const float* bk      = (const float*)d_in[5];
    const float* Wv      = (const float*)d_in[6];
    const float* bv      = (const float*)d_in[7];
    const float* gamma_q = (const float*)d_in[8];
    const float* beta_q  = (const float*)d_in[9];
    const float* gamma_v = (const float*)d_in[10];
    const float* beta_v  = (const float*)d_in[11];
    const float* pos_w   = (const float*)d_in[12];
    const float* pos_b   = (const float*)d_in[13];
    float* out = (float*)d_out;

    float *dQ, *dK, *dV, *dCLp, *dCL, *dqp, *dqb, *dqsc, *dqof, *dvsc, *dvof;
    cudaGetSymbolAddress((void**)&dQ,   g_Q);
    cudaGetSymbolAddress((void**)&dK,   g_K);
    cudaGetSymbolAddress((void**)&dV,   g_V);
    cudaGetSymbolAddress((void**)&dCLp, g_CLp);
    cudaGetSymbolAddress((void**)&dCL,  g_CL);
    cudaGetSymbolAddress((void**)&dqp,  g_qpos);
    cudaGetSymbolAddress((void**)&dqb,  g_qb);
    cudaGetSymbolAddress((void**)&dqsc, g_qsc);
    cudaGetSymbolAddress((void**)&dqof, g_qof);
    cudaGetSymbolAddress((void**)&dvsc, g_vsc);
    cudaGetSymbolAddress((void**)&dvof, g_vof);

    proj_all<<<dim3(Tc / 128, 1, 48), 128>>>(x, context, Wq, bq, Wk, bk, Wv, bv, dQ, dK, dV);
    normalize<<<832, 256>>>(dK, dQ, dV, gamma_q, beta_q, gamma_v, beta_v,
                            dqsc, dqof, dvsc, dvof);
    mid_kernel<<<384, 256>>>(dK, dV, dCLp, dQ, pos_w, pos_b, dqsc, dqof, dqp, dqb);
    cl_reduce<<<BKV / 256, 256>>>(dCLp, dCL, dvsc, dvof);
    out_kernel<<<dim3(Tc / 64, Vc / 32, Bc), 256>>>(dQ, dCL, dV, dqp, dqb,
                                                    dqsc, dqof, dvsc, dvof, out);
}

// round 10
// speedup vs baseline: 1.1663x; 1.1663x over previous
#include <cuda_runtime.h>
#include <cstdint>

#define Bc   8
#define CCc  512
#define Kc   64
#define Vc   256
#define Tc   1024
#define KSc  23
#define EPSc 1e-5f
#define BKV  (Bc * Kc * Vc)
#define NSPLIT 8

typedef unsigned long long u64t;

#define PACK2(d, v)  asm("mov.b64 %0, {%1, %1};" : "=l"(d) : "f"(v))
#define FMA2(d, a, b) asm("fma.rn.f32x2 %0, %1, %2, %0;" : "+l"(d) : "l"(a), "l"(b))
#define UNPACK2(lo, hi, in) asm("mov.b64 {%0, %1}, %2;" : "=f"(lo), "=f"(hi) : "l"(in))

// ---------------- scratch (device globals) ----------------
__device__ float g_Q[Bc * Kc * Tc];          // raw queries
__device__ float g_K[Bc * Kc * Tc];          // keys -> softmaxed in place
__device__ float g_V[Bc * Vc * Tc];          // raw values
__device__ float g_CLp[NSPLIT * BKV];        // split-T partials of content lambda
__device__ float g_CL[BKV];                  // content lambda (BN(V) folded in)
__device__ float g_qpos[Bc * Tc * KSc];      // qn @ pos_w
__device__ float g_qb[Bc * Tc];              // qn @ pos_b
__device__ float g_qsc[Kc], g_qof[Kc];       // BN(Q) affine
__device__ float g_vsc[Vc], g_vof[Vc];       // BN(V) affine

// ---------------- fused Q/K/V projection (f32x2 packed math) ----------------
// C[b][m][t] = sum_c W[m][c]*X[b][c][t] + bias[m]
// 128 threads, BM=64, BN=128, BK=16; per-thread 8m x 4 t-pairs.
__global__ void proj_all(const float* __restrict__ x, const float* __restrict__ ctx,
                         const float* __restrict__ Wq, const float* __restrict__ bq,
                         const float* __restrict__ Wk, const float* __restrict__ bk,
                         const float* __restrict__ Wv, const float* __restrict__ bv,
                         float* __restrict__ Qd, float* __restrict__ Kd,
                         float* __restrict__ Vd)
{
    const int z = blockIdx.z;
    const float *W, *Xb, *bias;
    float* C;
    int b, m0;
    if (z < 8)        { b = z;      m0 = 0;            W = Wq; bias = bq; Xb = x;   C = Qd + (size_t)b * Kc * Tc; }
    else if (z < 16)  { b = z - 8;  m0 = 0;            W = Wk; bias = bk; Xb = ctx; C = Kd + (size_t)b * Kc * Tc; }
    else { int zz = z - 16; b = zz >> 2; m0 = (zz & 3) * 64; W = Wv; bias = bv; Xb = ctx; C = Vd + (size_t)b * Vc * Tc; }
    const float* X = Xb + (size_t)b * CCc * Tc;
    const int n0 = blockIdx.x * 128;

    __shared__ float Ws[16][72];
    __shared__ float Xs[16][128];

    const int tid = threadIdx.x;       // 128
    const int tr = tid >> 4;           // 0..7
    const int tc = tid & 15;           // 0..15

    u64t acc[8][4];
#pragma unroll
    for (int i = 0; i < 8; i++)
#pragma unroll
        for (int q = 0; q < 4; q++) acc[i][q] = 0ULL;

    for (int c0 = 0; c0 < CCc; c0 += 16) {
#pragma unroll
        for (int f = tid; f < 256; f += 128) {
            int mm = f >> 2, c4 = f & 3;
            float4 w = *reinterpret_cast<const float4*>(&W[(size_t)(m0 + mm) * CCc + c0 + c4 * 4]);
            Ws[c4 * 4 + 0][mm] = w.x;
            Ws[c4 * 4 + 1][mm] = w.y;
            Ws[c4 * 4 + 2][mm] = w.z;
            Ws[c4 * 4 + 3][mm] = w.w;
        }
#pragma unroll
        for (int f = tid; f < 512; f += 128) {
            int kk = f >> 5, n4 = f & 31;
            *reinterpret_cast<float4*>(&Xs[kk][n4 * 4]) =
                *reinterpret_cast<const float4*>(&X[(size_t)(c0 + kk) * Tc + n0 + n4 * 4]);
        }
        __syncthreads();
#pragma unroll
        for (int kk = 0; kk < 16; kk++) {
            const u64t* xp = reinterpret_cast<const u64t*>(&Xs[kk][tc * 8]);
            u64t xv[4] = {xp[0], xp[1], xp[2], xp[3]};
            float4 a0 = *reinterpret_cast<const float4*>(&Ws[kk][tr * 8]);
            float4 a1 = *reinterpret_cast<const float4*>(&Ws[kk][tr * 8 + 4]);
            u64t av[8];
            PACK2(av[0], a0.x); PACK2(av[1], a0.y); PACK2(av[2], a0.z); PACK2(av[3], a0.w);
            PACK2(av[4], a1.x); PACK2(av[5], a1.y); PACK2(av[6], a1.z); PACK2(av[7], a1.w);
#pragma unroll
            for (int i = 0; i < 8; i++)
#pragma unroll
                for (int q = 0; q < 4; q++) FMA2(acc[i][q], av[i], xv[q]);
        }
        __syncthreads();
    }
#pragma unroll
    for (int i = 0; i < 8; i++) {
        int m = m0 + tr * 8 + i;
        float bi = bias[m];
        float* cr = C + (size_t)m * Tc + n0 + tc * 8;
        float o[8];
#pragma unroll
        for (int q = 0; q < 4; q++) UNPACK2(o[2 * q], o[2 * q + 1], acc[i][q]);
        float4 o0 = {o[0] + bi, o[1] + bi, o[2] + bi, o[3] + bi};
        float4 o1 = {o[4] + bi, o[5] + bi, o[6] + bi, o[7] + bi};
        *reinterpret_cast<float4*>(cr)     = o0;
        *reinterpret_cast<float4*>(cr + 4) = o1;
    }
}

// ---------------- fused normalize: softmax(K) in place + BN stats for Q,V ----
__global__ void normalize(float* __restrict__ Kd, const float* __restrict__ Qd,
                          const float* __restrict__ Vd,
                          const float* __restrict__ gq, const float* __restrict__ bq,
                          const float* __restrict__ gv, const float* __restrict__ bv,
                          float* __restrict__ qsc, float* __restrict__ qof,
                          float* __restrict__ vsc, float* __restrict__ vof)
{
    const int tid = threadIdx.x;
    __shared__ float rs[256], rq[256];

    if (blockIdx.x < 512) {
        float* r = Kd + (size_t)blockIdx.x * Tc;
        float v[4];
        float m = -1e30f;
#pragma unroll
        for (int j = 0; j < 4; j++) { v[j] = r[tid + j * 256]; m = fmaxf(m, v[j]); }
        rs[tid] = m; __syncthreads();
        for (int s = 128; s > 0; s >>= 1) {
            if (tid < s) rs[tid] = fmaxf(rs[tid], rs[tid + s]);
            __syncthreads();
        }
        m = rs[0]; __syncthreads();
        float sum = 0.f;
#pragma unroll
        for (int j = 0; j < 4; j++) { v[j] = expf(v[j] - m); sum += v[j]; }
        rs[tid] = sum; __syncthreads();
        for (int s = 128; s > 0; s >>= 1) {
            if (tid < s) rs[tid] += rs[tid + s];
            __syncthreads();
        }
        float inv = 1.f / rs[0];
#pragma unroll
        for (int j = 0; j < 4; j++) r[tid + j * 256] = v[j] * inv;
        return;
    }

    const float* data;
    const float *gamma, *beta;
    float *osc, *oof;
    int c, C;
    if (blockIdx.x < 576) { c = blockIdx.x - 512; C = Kc; data = Qd; gamma = gq; beta = bq; osc = qsc; oof = qof; }
    else                  { c = blockIdx.x - 576; C = Vc; data = Vd; gamma = gv; beta = bv; osc = vsc; oof = vof; }

    float s = 0.f, sq = 0.f;
    for (int i = tid; i < Bc * Tc; i += 256) {
        int b = i >> 10, t = i & 1023;
        float z = data[((size_t)b * C + c) * Tc + t];
        s += z; sq += z * z;
    }
    rs[tid] = s; rq[tid] = sq; __syncthreads();
    for (int st = 128; st > 0; st >>= 1) {
        if (tid < st) { rs[tid] += rs[tid + st]; rq[tid] += rq[tid + st]; }
        __syncthreads();
    }
    if (tid == 0) {
        const float invN = 1.f / (Bc * Tc);
        float mean = rs[0] * invN;
        float var  = rq[0] * invN - mean * mean;
        float g  = gamma[c] * rsqrtf(var + EPSc);
        osc[c] = g;
        oof[c] = beta[c] - mean * g;
    }
}

// ---------------- mid kernel: cl_part (blocks 0..255) + qpos (blocks 256..383)
__global__ void __launch_bounds__(256, 4)
mid_kernel(const float* __restrict__ Kn, const float* __restrict__ Vr,
           float* __restrict__ CLp,
           const float* __restrict__ Qr, const float* __restrict__ pos_w,
           const float* __restrict__ pos_b,
           const float* __restrict__ qsc, const float* __restrict__ qof,
           float* __restrict__ qpos, float* __restrict__ qb)
{
    __shared__ float smem[5728];
    const int tid = threadIdx.x;   // 256

    if (blockIdx.x < 256) {
        const int xid = blockIdx.x;
        const int v0 = (xid & 3) * 64;
        const int b  = (xid >> 2) & 7;
        const int ts = xid >> 5;         // 0..7
        const float* Ab = Kn + (size_t)b * Kc * Tc;
        const float* Vb = Vr + (size_t)b * Vc * Tc;

        float* As = smem;            // [32][65]
        float* Bs = smem + 2080;     // [32][66]

        const int tr = tid >> 4;
        const int tc = tid & 15;

        u64t acc[4][2];
#pragma unroll
        for (int i = 0; i < 4; i++) { acc[i][0] = 0ULL; acc[i][1] = 0ULL; }

        for (int t0 = ts * 128; t0 < ts * 128 + 128; t0 += 32) {
#pragma unroll
            for (int i = tid; i < 64 * 32; i += 256) {
                int r = i >> 5, tt = i & 31;
                As[tt * 65 + r] = Ab[(size_t)r * Tc + t0 + tt];
                Bs[tt * 66 + r] = Vb[(size_t)(v0 + r) * Tc + t0 + tt];
            }
            __syncthreads();
#pragma unroll
            for (int tt = 0; tt < 32; tt++) {
                const float* ar = &As[tt * 65 + tr * 4];
                const u64t* br = reinterpret_cast<const u64t*>(&Bs[tt * 66 + tc * 4]);
                u64t b0 = br[0], b1 = br[1];
                u64t a2[4];
                PACK2(a2[0], ar[0]); PACK2(a2[1], ar[1]);
                PACK2(a2[2], ar[2]); PACK2(a2[3], ar[3]);
#pragma unroll
                for (int i = 0; i < 4; i++) {
                    FMA2(acc[i][0], a2[i], b0);
                    FMA2(acc[i][1], a2[i], b1);
                }
            }
            __syncthreads();
        }
        float* Cb = CLp + (size_t)ts * BKV + (size_t)b * Kc * Vc;
#pragma unroll
        for (int i = 0; i < 4; i++) {
            float o[4];
            UNPACK2(o[0], o[1], acc[i][0]);
            UNPACK2(o[2], o[3], acc[i][1]);
            *reinterpret_cast<float4*>(&Cb[(size_t)(tr * 4 + i) * Vc + v0 + tc * 4]) =
                make_float4(o[0], o[1], o[2], o[3]);
        }
    } else {
        const int idx = blockIdx.x - 256;
        const int t0 = (idx & 15) * 64;
        const int b  = idx >> 4;

        float* Qs  = smem;                      // [64][65]
        float* pws = smem + 64 * 65;            // [64][24]
        float* cs  = smem + 64 * 65 + 64 * 24;  // [24]

        for (int i = tid; i < 64 * 64; i += 256) {
            int k = i >> 6, t = i & 63;
            Qs[k * 65 + t] = Qr[((size_t)b * Kc + k) * Tc + t0 + t];
        }
        for (int i = tid; i < Kc * KSc; i += 256) {
            int k = i / KSc, s = i % KSc;
            pws[k * 24 + s] = qsc[k] * pos_w[k * KSc + s];
        }
        if (tid < Kc) pws[tid * 24 + 23] = qsc[tid] * pos_b[tid];
        if (tid < 24) {
            float c = 0.f;
            if (tid < 23) {
                for (int k = 0; k < Kc; k++) c += qof[k] * pos_w[k * KSc + tid];
            } else {
                for (int k = 0; k < Kc; k++) c += qof[k] * pos_b[k];
            }
            cs[tid] = c;
        }
        __syncthreads();

        const int t  = tid & 63;
        const int sg = tid >> 6;

        float acc[6];
#pragma unroll
        for (int j = 0; j < 6; j++) acc[j] = cs[sg * 6 + j];

#pragma unroll 8
        for (int k = 0; k < Kc; k++) {
            float q = Qs[k * 65 + t];
#pragma unroll
            for (int j = 0; j < 6; j++) acc[j] += q * pws[k * 24 + sg * 6 + j];
        }
#pragma unroll
        for (int j = 0; j < 6; j++) {
            int slot = sg * 6 + j;
            if (slot < 23) qpos[((size_t)b * Tc + t0 + t) * KSc + slot] = acc[j];
            else           qb[(size_t)b * Tc + t0 + t] = acc[j];
        }
    }
}

// CL = vsc[v]*(sum of 8 partials) + vof[v]
__global__ void cl_reduce(const float* __restrict__ CLp, float* __restrict__ CL,
                          const float* __restrict__ vsc, const float* __restrict__ vof)
{
    int i = blockIdx.x * 256 + threadIdx.x;
    int v = i & (Vc - 1);
    float s = 0.f;
#pragma unroll
    for (int p = 0; p < NSPLIT; p++) s += CLp[i + (size_t)p * BKV];
    CL[i] = s * vsc[v] + vof[v];
}

// ---------------- fused output (content + positional, all packed f32x2) ------
__global__ void out_kernel(const float* __restrict__ Qr, const float* __restrict__ CL,
                           const float* __restrict__ Vr, const float* __restrict__ qpos,
                           const float* __restrict__ qb,
                           const float* __restrict__ qsc, const float* __restrict__ qof,
                           const float* __restrict__ vsc, const float* __restrict__ vof,
                           float* __restrict__ out)
{
    const int b  = blockIdx.z;
    const int v0 = blockIdx.y * 32;
    const int t0 = blockIdx.x * 64;
    const int tid = threadIdx.x;
    const int tl = tid & 63;
    const int vlane = tid >> 6;

    __shared__ float Qs[64][64];
    __shared__ float cls[64][32];
    __shared__ float qps[64][25];
    __shared__ float Vs[86][34];    // transposed: [t-idx][v], pad 34 for 8B align
    __shared__ float qsS[64], qoS[64], vsS[32], voS[32];

    if (tid < 64) { qsS[tid] = qsc[tid]; qoS[tid] = qof[tid]; }
    else if (tid < 96)  { vsS[tid - 64] = vsc[v0 + tid - 64]; }
    else if (tid < 128) { voS[tid - 96] = vof[v0 + tid - 96]; }
    __syncthreads();

#pragma unroll 4
    for (int i = tid; i < 64 * 64; i += 256) {
        int k = i >> 6, t = i & 63;
        Qs[k][t] = Qr[((size_t)b * Kc + k) * Tc + t0 + t] * qsS[k] + qoS[k];
    }
#pragma unroll 2
    for (int i = tid; i < 64 * 32; i += 256) {
        int k = i >> 5, vv = i & 31;
        cls[k][vv] = CL[((size_t)b * Kc + k) * Vc + v0 + vv];
    }
    for (int i = tid; i < 64 * KSc; i += 256) {
        int t = i / KSc, s = i % KSc;
        qps[t][s] = qpos[((size_t)b * Tc + t0 + t) * KSc + s];
    }
    if (tid < 64) qps[tid][23] = qb[b * Tc + t0 + tid];
    for (int i = tid; i < 32 * 86; i += 256) {
        int vv = i / 86, idx = i % 86;      // coalesced global read over idx
        int tg = t0 - 11 + idx;
        Vs[idx][vv] = (tg >= 0 && tg < Tc)
                          ? Vr[((size_t)b * Vc + v0 + vv) * Tc + tg] * vsS[vv] + voS[vv]
                          : 0.f;
    }
    __syncthreads();

    u64t accp[4];
#pragma unroll
    for (int q = 0; q < 4; q++) accp[q] = 0ULL;

    // content: out += Q^T . CL over k
#pragma unroll
    for (int k = 0; k < Kc; k++) {
        u64t qv;
        PACK2(qv, Qs[k][tl]);
        const u64t* cp = reinterpret_cast<const u64t*>(&cls[k][vlane * 8]);
#pragma unroll
        for (int q = 0; q < 4; q++) FMA2(accp[q], qv, cp[q]);
    }

    // positional: out += sum_s qpos[t][s] * Vn[v][t+s-11]  (v contiguous)
#pragma unroll
    for (int s = 0; s < KSc; s++) {
        u64t qd;
        PACK2(qd, qps[tl][s]);
        const u64t* vp = reinterpret_cast<const u64t*>(&Vs[tl + s][vlane * 8]);
#pragma unroll
        for (int q = 0; q < 4; q++) FMA2(accp[q], qd, vp[q]);
    }

    float acc[8];
#pragma unroll
    for (int q = 0; q < 4; q++) UNPACK2(acc[2 * q], acc[2 * q + 1], accp[q]);

    float qbv = qps[tl][23];
#pragma unroll
    for (int j = 0; j < 8; j++)
        out[((size_t)b * Vc + v0 + vlane * 8 + j) * Tc + t0 + tl] = acc[j] + qbv;
}

// ---------------- launch ----------------
extern "C" void kernel_launch(void* const* d_in, const int* in_sizes, int n_in,
                              void* d_out, int out_size)
{
    const float* x       = (const float*)d_in[0];
    const float* context = (const float*)d_in[1];
    const float* Wq      = (const float*)d_in[2];
    const float* bq      = (const float*)d_in[3];
    const float* Wk      = (const float*)d_in[4];
    const float* bk      = (const float*)d_in[5];
    const float* Wv      = (const float*)d_in[6];
    const float* bv      = (const float*)d_in[7];
    const float* gamma_q = (const float*)d_in[8];
    const float* beta_q  = (const float*)d_in[9];
    const float* gamma_v = (const float*)d_in[10];
    const float* beta_v  = (const float*)d_in[11];
    const float* pos_w   = (const float*)d_in[12];
    const float* pos_b   = (const float*)d_in[13];
    float* out = (float*)d_out;

    float *dQ, *dK, *dV, *dCLp, *dCL, *dqp, *dqb, *dqsc, *dqof, *dvsc, *dvof;
    cudaGetSymbolAddress((void**)&dQ,   g_Q);
    cudaGetSymbolAddress((void**)&dK,   g_K);
    cudaGetSymbolAddress((void**)&dV,   g_V);
    cudaGetSymbolAddress((void**)&dCLp, g_CLp);
    cudaGetSymbolAddress((void**)&dCL,  g_CL);
    cudaGetSymbolAddress((void**)&dqp,  g_qpos);
    cudaGetSymbolAddress((void**)&dqb,  g_qb);
    cudaGetSymbolAddress((void**)&dqsc, g_qsc);
    cudaGetSymbolAddress((void**)&dqof, g_qof);
    cudaGetSymbolAddress((void**)&dvsc, g_vsc);
    cudaGetSymbolAddress((void**)&dvof, g_vof);

    proj_all<<<dim3(Tc / 128, 1, 48), 128>>>(x, context, Wq, bq, Wk, bk, Wv, bv, dQ, dK, dV);
    normalize<<<832, 256>>>(dK, dQ, dV, gamma_q, beta_q, gamma_v, beta_v,
                            dqsc, dqof, dvsc, dvof);
    mid_kernel<<<384, 256>>>(dK, dV, dCLp, dQ, pos_w, pos_b, dqsc, dqof, dqp, dqb);
    cl_reduce<<<BKV / 256, 256>>>(dCLp, dCL, dvsc, dvof);
    out_kernel<<<dim3(Tc / 64, Vc / 32, Bc), 256>>>(dQ, dCL, dV, dqp, dqb,
                                                    dqsc, dqof, dvsc, dvof, out);
}

// round 11
// speedup vs baseline: 1.1843x; 1.0154x over previous
#include <cuda_runtime.h>
#include <cstdint>

#define Bc   8
#define CCc  512
#define Kc   64
#define Vc   256
#define Tc   1024
#define KSc  23
#define EPSc 1e-5f
#define BKV  (Bc * Kc * Vc)
#define NSPLIT 8

typedef unsigned long long u64t;

#define PACK2(d, v)  asm("mov.b64 %0, {%1, %1};" : "=l"(d) : "f"(v))
#define FMA2(d, a, b) asm("fma.rn.f32x2 %0, %1, %2, %0;" : "+l"(d) : "l"(a), "l"(b))
#define UNPACK2(lo, hi, in) asm("mov.b64 {%0, %1}, %2;" : "=f"(lo), "=f"(hi) : "l"(in))

// ---------------- scratch (device globals) ----------------
__device__ float g_Q[Bc * Kc * Tc];          // raw queries
__device__ float g_K[Bc * Kc * Tc];          // keys -> softmaxed in place
__device__ float g_V[Bc * Vc * Tc];          // raw values
__device__ float g_CLp[NSPLIT * BKV];        // split-T partials of content lambda
__device__ float g_CL[BKV];                  // content lambda (BN(V) folded in)
__device__ float g_qpos[Bc * Tc * KSc];      // qn @ pos_w
__device__ float g_qb[Bc * Tc];              // qn @ pos_b
__device__ float g_qsc[Kc], g_qof[Kc];       // BN(Q) affine
__device__ float g_vsc[Vc], g_vof[Vc];       // BN(V) affine

// ---------------- fused Q/K/V projection (f32x2 packed math) ----------------
__global__ void proj_all(const float* __restrict__ x, const float* __restrict__ ctx,
                         const float* __restrict__ Wq, const float* __restrict__ bq,
                         const float* __restrict__ Wk, const float* __restrict__ bk,
                         const float* __restrict__ Wv, const float* __restrict__ bv,
                         float* __restrict__ Qd, float* __restrict__ Kd,
                         float* __restrict__ Vd)
{
    const int z = blockIdx.z;
    const float *W, *Xb, *bias;
    float* C;
    int b, m0;
    if (z < 8)        { b = z;      m0 = 0;            W = Wq; bias = bq; Xb = x;   C = Qd + (size_t)b * Kc * Tc; }
    else if (z < 16)  { b = z - 8;  m0 = 0;            W = Wk; bias = bk; Xb = ctx; C = Kd + (size_t)b * Kc * Tc; }
    else { int zz = z - 16; b = zz >> 2; m0 = (zz & 3) * 64; W = Wv; bias = bv; Xb = ctx; C = Vd + (size_t)b * Vc * Tc; }
    const float* X = Xb + (size_t)b * CCc * Tc;
    const int n0 = blockIdx.x * 128;

    __shared__ float Ws[16][72];
    __shared__ float Xs[16][128];

    const int tid = threadIdx.x;       // 128
    const int tr = tid >> 4;           // 0..7
    const int tc = tid & 15;           // 0..15

    u64t acc[8][4];
#pragma unroll
    for (int i = 0; i < 8; i++)
#pragma unroll
        for (int q = 0; q < 4; q++) acc[i][q] = 0ULL;

    for (int c0 = 0; c0 < CCc; c0 += 16) {
#pragma unroll
        for (int f = tid; f < 256; f += 128) {
            int mm = f >> 2, c4 = f & 3;
            float4 w = *reinterpret_cast<const float4*>(&W[(size_t)(m0 + mm) * CCc + c0 + c4 * 4]);
            Ws[c4 * 4 + 0][mm] = w.x;
            Ws[c4 * 4 + 1][mm] = w.y;
            Ws[c4 * 4 + 2][mm] = w.z;
            Ws[c4 * 4 + 3][mm] = w.w;
        }
#pragma unroll
        for (int f = tid; f < 512; f += 128) {
            int kk = f >> 5, n4 = f & 31;
            *reinterpret_cast<float4*>(&Xs[kk][n4 * 4]) =
                *reinterpret_cast<const float4*>(&X[(size_t)(c0 + kk) * Tc + n0 + n4 * 4]);
        }
        __syncthreads();
#pragma unroll
        for (int kk = 0; kk < 16; kk++) {
            const u64t* xp = reinterpret_cast<const u64t*>(&Xs[kk][tc * 8]);
            u64t xv[4] = {xp[0], xp[1], xp[2], xp[3]};
            float4 a0 = *reinterpret_cast<const float4*>(&Ws[kk][tr * 8]);
            float4 a1 = *reinterpret_cast<const float4*>(&Ws[kk][tr * 8 + 4]);
            u64t av[8];
            PACK2(av[0], a0.x); PACK2(av[1], a0.y); PACK2(av[2], a0.z); PACK2(av[3], a0.w);
            PACK2(av[4], a1.x); PACK2(av[5], a1.y); PACK2(av[6], a1.z); PACK2(av[7], a1.w);
#pragma unroll
            for (int i = 0; i < 8; i++)
#pragma unroll
                for (int q = 0; q < 4; q++) FMA2(acc[i][q], av[i], xv[q]);
        }
        __syncthreads();
    }
#pragma unroll
    for (int i = 0; i < 8; i++) {
        int m = m0 + tr * 8 + i;
        float bi = bias[m];
        float* cr = C + (size_t)m * Tc + n0 + tc * 8;
        float o[8];
#pragma unroll
        for (int q = 0; q < 4; q++) UNPACK2(o[2 * q], o[2 * q + 1], acc[i][q]);
        float4 o0 = {o[0] + bi, o[1] + bi, o[2] + bi, o[3] + bi};
        float4 o1 = {o[4] + bi, o[5] + bi, o[6] + bi, o[7] + bi};
        *reinterpret_cast<float4*>(cr)     = o0;
        *reinterpret_cast<float4*>(cr + 4) = o1;
    }
}

// ---------------- fused normalize: softmax(K) in place + BN stats for Q,V ----
__global__ void normalize(float* __restrict__ Kd, const float* __restrict__ Qd,
                          const float* __restrict__ Vd,
                          const float* __restrict__ gq, const float* __restrict__ bq,
                          const float* __restrict__ gv, const float* __restrict__ bv,
                          float* __restrict__ qsc, float* __restrict__ qof,
                          float* __restrict__ vsc, float* __restrict__ vof)
{
    const int tid = threadIdx.x;
    __shared__ float rs[256], rq[256];

    if (blockIdx.x < 512) {
        float* r = Kd + (size_t)blockIdx.x * Tc;
        float v[4];
        float m = -1e30f;
#pragma unroll
        for (int j = 0; j < 4; j++) { v[j] = r[tid + j * 256]; m = fmaxf(m, v[j]); }
        rs[tid] = m; __syncthreads();
        for (int s = 128; s > 0; s >>= 1) {
            if (tid < s) rs[tid] = fmaxf(rs[tid], rs[tid + s]);
            __syncthreads();
        }
        m = rs[0]; __syncthreads();
        float sum = 0.f;
#pragma unroll
        for (int j = 0; j < 4; j++) { v[j] = expf(v[j] - m); sum += v[j]; }
        rs[tid] = sum; __syncthreads();
        for (int s = 128; s > 0; s >>= 1) {
            if (tid < s) rs[tid] += rs[tid + s];
            __syncthreads();
        }
        float inv = 1.f / rs[0];
#pragma unroll
        for (int j = 0; j < 4; j++) r[tid + j * 256] = v[j] * inv;
        return;
    }

    const float* data;
    const float *gamma, *beta;
    float *osc, *oof;
    int c, C;
    if (blockIdx.x < 576) { c = blockIdx.x - 512; C = Kc; data = Qd; gamma = gq; beta = bq; osc = qsc; oof = qof; }
    else                  { c = blockIdx.x - 576; C = Vc; data = Vd; gamma = gv; beta = bv; osc = vsc; oof = vof; }

    float s = 0.f, sq = 0.f;
    for (int i = tid; i < Bc * Tc; i += 256) {
        int b = i >> 10, t = i & 1023;
        float z = data[((size_t)b * C + c) * Tc + t];
        s += z; sq += z * z;
    }
    rs[tid] = s; rq[tid] = sq; __syncthreads();
    for (int st = 128; st > 0; st >>= 1) {
        if (tid < st) { rs[tid] += rs[tid + st]; rq[tid] += rq[tid + st]; }
        __syncthreads();
    }
    if (tid == 0) {
        const float invN = 1.f / (Bc * Tc);
        float mean = rs[0] * invN;
        float var  = rq[0] * invN - mean * mean;
        float g  = gamma[c] * rsqrtf(var + EPSc);
        osc[c] = g;
        oof[c] = beta[c] - mean * g;
    }
}

// ---------------- mid kernel: cl_part (blocks 0..255) + qpos (blocks 256..383)
__global__ void __launch_bounds__(256, 4)
mid_kernel(const float* __restrict__ Kn, const float* __restrict__ Vr,
           float* __restrict__ CLp,
           const float* __restrict__ Qr, const float* __restrict__ pos_w,
           const float* __restrict__ pos_b,
           const float* __restrict__ qsc, const float* __restrict__ qof,
           float* __restrict__ qpos, float* __restrict__ qb)
{
    __shared__ float smem[5728];
    const int tid = threadIdx.x;   // 256

    if (blockIdx.x < 256) {
        const int xid = blockIdx.x;
        const int v0 = (xid & 3) * 64;
        const int b  = (xid >> 2) & 7;
        const int ts = xid >> 5;         // 0..7
        const float* Ab = Kn + (size_t)b * Kc * Tc;
        const float* Vb = Vr + (size_t)b * Vc * Tc;

        float* As = smem;            // [32][65]
        float* Bs = smem + 2080;     // [32][66]

        const int tr = tid >> 4;
        const int tc = tid & 15;

        u64t acc[4][2];
#pragma unroll
        for (int i = 0; i < 4; i++) { acc[i][0] = 0ULL; acc[i][1] = 0ULL; }

        for (int t0 = ts * 128; t0 < ts * 128 + 128; t0 += 32) {
#pragma unroll
            for (int i = tid; i < 64 * 32; i += 256) {
                int r = i >> 5, tt = i & 31;
                As[tt * 65 + r] = Ab[(size_t)r * Tc + t0 + tt];
                Bs[tt * 66 + r] = Vb[(size_t)(v0 + r) * Tc + t0 + tt];
            }
            __syncthreads();
#pragma unroll
            for (int tt = 0; tt < 32; tt++) {
                const float* ar = &As[tt * 65 + tr * 4];
                const u64t* br = reinterpret_cast<const u64t*>(&Bs[tt * 66 + tc * 4]);
                u64t b0 = br[0], b1 = br[1];
                u64t a2[4];
                PACK2(a2[0], ar[0]); PACK2(a2[1], ar[1]);
                PACK2(a2[2], ar[2]); PACK2(a2[3], ar[3]);
#pragma unroll
                for (int i = 0; i < 4; i++) {
                    FMA2(acc[i][0], a2[i], b0);
                    FMA2(acc[i][1], a2[i], b1);
                }
            }
            __syncthreads();
        }
        float* Cb = CLp + (size_t)ts * BKV + (size_t)b * Kc * Vc;
#pragma unroll
        for (int i = 0; i < 4; i++) {
            float o[4];
            UNPACK2(o[0], o[1], acc[i][0]);
            UNPACK2(o[2], o[3], acc[i][1]);
            *reinterpret_cast<float4*>(&Cb[(size_t)(tr * 4 + i) * Vc + v0 + tc * 4]) =
                make_float4(o[0], o[1], o[2], o[3]);
        }
    } else {
        const int idx = blockIdx.x - 256;
        const int t0 = (idx & 15) * 64;
        const int b  = idx >> 4;

        float* Qs  = smem;                      // [64][65]
        float* pws = smem + 64 * 65;            // [64][24]
        float* cs  = smem + 64 * 65 + 64 * 24;  // [24]

        for (int i = tid; i < 64 * 64; i += 256) {
            int k = i >> 6, t = i & 63;
            Qs[k * 65 + t] = Qr[((size_t)b * Kc + k) * Tc + t0 + t];
        }
        for (int i = tid; i < Kc * KSc; i += 256) {
            int k = i / KSc, s = i % KSc;
            pws[k * 24 + s] = qsc[k] * pos_w[k * KSc + s];
        }
        if (tid < Kc) pws[tid * 24 + 23] = qsc[tid] * pos_b[tid];
        if (tid < 24) {
            float c = 0.f;
            if (tid < 23) {
                for (int k = 0; k < Kc; k++) c += qof[k] * pos_w[k * KSc + tid];
            } else {
                for (int k = 0; k < Kc; k++) c += qof[k] * pos_b[k];
            }
            cs[tid] = c;
        }
        __syncthreads();

        const int t  = tid & 63;
        const int sg = tid >> 6;

        float acc[6];
#pragma unroll
        for (int j = 0; j < 6; j++) acc[j] = cs[sg * 6 + j];

#pragma unroll 8
        for (int k = 0; k < Kc; k++) {
            float q = Qs[k * 65 + t];
#pragma unroll
            for (int j = 0; j < 6; j++) acc[j] += q * pws[k * 24 + sg * 6 + j];
        }
#pragma unroll
        for (int j = 0; j < 6; j++) {
            int slot = sg * 6 + j;
            if (slot < 23) qpos[((size_t)b * Tc + t0 + t) * KSc + slot] = acc[j];
            else           qb[(size_t)b * Tc + t0 + t] = acc[j];
        }
    }
}

// CL = vsc[v]*(sum of 8 partials) + vof[v]
__global__ void cl_reduce(const float* __restrict__ CLp, float* __restrict__ CL,
                          const float* __restrict__ vsc, const float* __restrict__ vof)
{
    int i = blockIdx.x * 256 + threadIdx.x;
    int v = i & (Vc - 1);
    float s = 0.f;
#pragma unroll
    for (int p = 0; p < NSPLIT; p++) s += CLp[i + (size_t)p * BKV];
    CL[i] = s * vsc[v] + vof[v];
}

// ---------------- fused output: v-block 64, dynamic smem, packed f32x2 -------
// out[b][v][t] = sum_k Qn[k][t]*CL[k][v] + sum_s qpos[t][s]*Vn[v][t+s-11] + qb[t]
__global__ void out_kernel(const float* __restrict__ Qr, const float* __restrict__ CL,
                           const float* __restrict__ Vr, const float* __restrict__ qpos,
                           const float* __restrict__ qb,
                           const float* __restrict__ qsc, const float* __restrict__ qof,
                           const float* __restrict__ vsc, const float* __restrict__ vof,
                           float* __restrict__ out)
{
    extern __shared__ float dsm[];
    float* Qs  = dsm;              // [64][64]
    float* cls = dsm + 4096;       // [64][64]  (k rows, v cols)
    float* qps = dsm + 8192;       // [64][25]
    float* Vs  = dsm + 9792;       // [86][70]  transposed, pad 70 (2-way max)
    float* qsS = dsm + 15812;      // [64]
    float* qoS = dsm + 15876;      // [64]
    float* vsS = dsm + 15940;      // [64]
    float* voS = dsm + 16004;      // [64]

    const int b  = blockIdx.z;
    const int v0 = blockIdx.y * 64;
    const int t0 = blockIdx.x * 64;
    const int tid = threadIdx.x;
    const int tl = tid & 63;       // t within tile
    const int vlane = tid >> 6;    // 0..3; each covers 16 v

    if (tid < 64)        { qsS[tid] = qsc[tid]; qoS[tid] = qof[tid]; }
    else if (tid < 128)  { vsS[tid - 64] = vsc[v0 + tid - 64]; }
    else if (tid < 192)  { voS[tid - 128] = vof[v0 + tid - 128]; }
    __syncthreads();

#pragma unroll 4
    for (int i = tid; i < 64 * 64; i += 256) {
        int k = i >> 6, t = i & 63;
        Qs[k * 64 + t] = Qr[((size_t)b * Kc + k) * Tc + t0 + t] * qsS[k] + qoS[k];
    }
#pragma unroll 4
    for (int i = tid; i < 64 * 64; i += 256) {
        int k = i >> 6, vv = i & 63;
        cls[k * 64 + vv] = CL[((size_t)b * Kc + k) * Vc + v0 + vv];
    }
    for (int i = tid; i < 64 * KSc; i += 256) {
        int t = i / KSc, s = i % KSc;
        qps[t * 25 + s] = qpos[((size_t)b * Tc + t0 + t) * KSc + s];
    }
    if (tid < 64) qps[tid * 25 + 23] = qb[b * Tc + t0 + tid];
#pragma unroll 4
    for (int i = tid; i < 64 * 86; i += 256) {
        int vv = i / 86, idx = i % 86;      // coalesced global over idx
        int tg = t0 - 11 + idx;
        Vs[idx * 70 + vv] = (tg >= 0 && tg < Tc)
                                ? Vr[((size_t)b * Vc + v0 + vv) * Tc + tg] * vsS[vv] + voS[vv]
                                : 0.f;
    }
    __syncthreads();

    u64t accp[8];
#pragma unroll
    for (int q = 0; q < 8; q++) accp[q] = 0ULL;

    // content: out += Q^T . CL over k   (cls reads broadcast within warp)
#pragma unroll
    for (int k = 0; k < Kc; k++) {
        u64t qv;
        PACK2(qv, Qs[k * 64 + tl]);
        const u64t* cp = reinterpret_cast<const u64t*>(&cls[k * 64 + vlane * 16]);
#pragma unroll
        for (int q = 0; q < 8; q++) FMA2(accp[q], qv, cp[q]);
    }

    // positional: out += sum_s qpos[t][s] * Vn[v][t+s-11]  (v contiguous)
#pragma unroll
    for (int s = 0; s < KSc; s++) {
        u64t qd;
        PACK2(qd, qps[tl * 25 + s]);
        const u64t* vp = reinterpret_cast<const u64t*>(&Vs[(tl + s) * 70 + vlane * 16]);
#pragma unroll
        for (int q = 0; q < 8; q++) FMA2(accp[q], qd, vp[q]);
    }

    float qbv = qps[tl * 25 + 23];
#pragma unroll
    for (int q = 0; q < 8; q++) {
        float lo, hi;
        UNPACK2(lo, hi, accp[q]);
        int v = v0 + vlane * 16 + 2 * q;
        out[((size_t)b * Vc + v) * Tc + t0 + tl]     = lo + qbv;
        out[((size_t)b * Vc + v + 1) * Tc + t0 + tl] = hi + qbv;
    }
}

// ---------------- launch ----------------
extern "C" void kernel_launch(void* const* d_in, const int* in_sizes, int n_in,
                              void* d_out, int out_size)
{
    const float* x       = (const float*)d_in[0];
    const float* context = (const float*)d_in[1];
    const float* Wq      = (const float*)d_in[2];
    const float* bq      = (const float*)d_in[3];
    const float* Wk      = (const float*)d_in[4];
    const float* bk      = (const float*)d_in[5];
    const float* Wv      = (const float*)d_in[6];
    const float* bv      = (const float*)d_in[7];
    const float* gamma_q = (const float*)d_in[8];
    const float* beta_q  = (const float*)d_in[9];
    const float* gamma_v = (const float*)d_in[10];
    const float* beta_v  = (const float*)d_in[11];
    const float* pos_w   = (const float*)d_in[12];
    const float* pos_b   = (const float*)d_in[13];
    float* out = (float*)d_out;

    float *dQ, *dK, *dV, *dCLp, *dCL, *dqp, *dqb, *dqsc, *dqof, *dvsc, *dvof;
    cudaGetSymbolAddress((void**)&dQ,   g_Q);
    cudaGetSymbolAddress((void**)&dK,   g_K);
    cudaGetSymbolAddress((void**)&dV,   g_V);
    cudaGetSymbolAddress((void**)&dCLp, g_CLp);
    cudaGetSymbolAddress((void**)&dCL,  g_CL);
    cudaGetSymbolAddress((void**)&dqp,  g_qpos);
    cudaGetSymbolAddress((void**)&dqb,  g_qb);
    cudaGetSymbolAddress((void**)&dqsc, g_qsc);
    cudaGetSymbolAddress((void**)&dqof, g_qof);
    cudaGetSymbolAddress((void**)&dvsc, g_vsc);
    cudaGetSymbolAddress((void**)&dvof, g_vof);

    const int OUT_SMEM = 16068 * 4;
    cudaFuncSetAttribute(out_kernel, cudaFuncAttributeMaxDynamicSharedMemorySize, OUT_SMEM);

    proj_all<<<dim3(Tc / 128, 1, 48), 128>>>(x, context, Wq, bq, Wk, bk, Wv, bv, dQ, dK, dV);
    normalize<<<832, 256>>>(dK, dQ, dV, gamma_q, beta_q, gamma_v, beta_v,
                            dqsc, dqof, dvsc, dvof);
    mid_kernel<<<384, 256>>>(dK, dV, dCLp, dQ, pos_w, pos_b, dqsc, dqof, dqp, dqb);
    cl_reduce<<<BKV / 256, 256>>>(dCLp, dCL, dvsc, dvof);
    out_kernel<<<dim3(Tc / 64, Vc / 64, Bc), 256, OUT_SMEM>>>(dQ, dCL, dV, dqp, dqb,
                                                              dqsc, dqof, dvsc, dvof, out);
}

// round 12
// speedup vs baseline: 1.2726x; 1.0746x over previous
#include <cuda_runtime.h>
#include <cstdint>

#define Bc   8
#define CCc  512
#define Kc   64
#define Vc   256
#define Tc   1024
#define KSc  23
#define EPSc 1e-5f
#define BKV  (Bc * Kc * Vc)
#define NSPLIT 8

typedef unsigned long long u64t;

#define PACK2(d, v)  asm("mov.b64 %0, {%1, %1};" : "=l"(d) : "f"(v))
#define FMA2(d, a, b) asm("fma.rn.f32x2 %0, %1, %2, %0;" : "+l"(d) : "l"(a), "l"(b))
#define UNPACK2(lo, hi, in) asm("mov.b64 {%0, %1}, %2;" : "=f"(lo), "=f"(hi) : "l"(in))

// ---------------- scratch (device globals) ----------------
__device__ float g_Q[Bc * Kc * Tc];          // raw queries
__device__ float g_K[Bc * Kc * Tc];          // keys -> softmaxed in place
__device__ float g_V[Bc * Vc * Tc];          // raw values
__device__ float g_CLp[NSPLIT * BKV];        // split-T partials of content lambda
__device__ float g_CL[BKV];                  // content lambda (BN(V) folded in)
__device__ float g_qpos[Bc * Tc * KSc];      // qn @ pos_w
__device__ float g_qb[Bc * Tc];              // qn @ pos_b
__device__ float g_qsc[Kc], g_qof[Kc];       // BN(Q) affine
__device__ float g_vsc[Vc], g_vof[Vc];       // BN(V) affine

// ---------------- fused Q/K/V projection (f32x2, double-buffered) -----------
// C[b][m][t] = sum_c W[m][c]*X[b][c][t] + bias[m]
// 128 threads, BM=64, BN=128, BK=16; per-thread 8m x 4 t-pairs.
__global__ void proj_all(const float* __restrict__ x, const float* __restrict__ ctx,
                         const float* __restrict__ Wq, const float* __restrict__ bq,
                         const float* __restrict__ Wk, const float* __restrict__ bk,
                         const float* __restrict__ Wv, const float* __restrict__ bv,
                         float* __restrict__ Qd, float* __restrict__ Kd,
                         float* __restrict__ Vd)
{
    const int z = blockIdx.z;
    const float *W, *Xb, *bias;
    float* C;
    int b, m0;
    if (z < 8)        { b = z;      m0 = 0;            W = Wq; bias = bq; Xb = x;   C = Qd + (size_t)b * Kc * Tc; }
    else if (z < 16)  { b = z - 8;  m0 = 0;            W = Wk; bias = bk; Xb = ctx; C = Kd + (size_t)b * Kc * Tc; }
    else { int zz = z - 16; b = zz >> 2; m0 = (zz & 3) * 64; W = Wv; bias = bv; Xb = ctx; C = Vd + (size_t)b * Vc * Tc; }
    const float* X = Xb + (size_t)b * CCc * Tc;
    const int n0 = blockIdx.x * 128;

    __shared__ float Ws[2][16][72];
    __shared__ float Xs[2][16][128];

    const int tid = threadIdx.x;       // 128
    const int tr = tid >> 4;           // 0..7
    const int tc = tid & 15;           // 0..15

    // per-thread load coords (fixed across chunks)
    const int wmm0 = tid >> 2,        wc40 = tid & 3;          // W elem 0 (f = tid)
    const int wmm1 = (tid + 128) >> 2, wc41 = tid & 3;         // W elem 1 (f = tid+128)
    const int xk0 = tid >> 5,          xn0 = (tid & 31) * 4;   // X rows f, f+128, f+256, f+384

    u64t acc[8][4];
#pragma unroll
    for (int i = 0; i < 8; i++)
#pragma unroll
        for (int q = 0; q < 4; q++) acc[i][q] = 0ULL;

    // load chunk 0 into buffer 0
    {
        float4 w0 = *reinterpret_cast<const float4*>(&W[(size_t)(m0 + wmm0) * CCc + wc40 * 4]);
        float4 w1 = *reinterpret_cast<const float4*>(&W[(size_t)(m0 + wmm1) * CCc + wc41 * 4]);
        Ws[0][wc40 * 4 + 0][wmm0] = w0.x; Ws[0][wc40 * 4 + 1][wmm0] = w0.y;
        Ws[0][wc40 * 4 + 2][wmm0] = w0.z; Ws[0][wc40 * 4 + 3][wmm0] = w0.w;
        Ws[0][wc41 * 4 + 0][wmm1] = w1.x; Ws[0][wc41 * 4 + 1][wmm1] = w1.y;
        Ws[0][wc41 * 4 + 2][wmm1] = w1.z; Ws[0][wc41 * 4 + 3][wmm1] = w1.w;
#pragma unroll
        for (int r = 0; r < 4; r++)
            *reinterpret_cast<float4*>(&Xs[0][xk0 + r * 4][xn0]) =
                *reinterpret_cast<const float4*>(&X[(size_t)(xk0 + r * 4) * Tc + n0 + xn0]);
    }
    __syncthreads();

    for (int ch = 0; ch < 32; ch++) {
        const int cur = ch & 1;
        float4 wpre0, wpre1, xpre[4];
        if (ch < 31) {
            const int c0 = (ch + 1) * 16;
            wpre0 = *reinterpret_cast<const float4*>(&W[(size_t)(m0 + wmm0) * CCc + c0 + wc40 * 4]);
            wpre1 = *reinterpret_cast<const float4*>(&W[(size_t)(m0 + wmm1) * CCc + c0 + wc41 * 4]);
#pragma unroll
            for (int r = 0; r < 4; r++)
                xpre[r] = *reinterpret_cast<const float4*>(&X[(size_t)(c0 + xk0 + r * 4) * Tc + n0 + xn0]);
        }
        // compute from buffer cur
#pragma unroll
        for (int kk = 0; kk < 16; kk++) {
            const u64t* xp = reinterpret_cast<const u64t*>(&Xs[cur][kk][tc * 8]);
            u64t xv[4] = {xp[0], xp[1], xp[2], xp[3]};
            float4 a0 = *reinterpret_cast<const float4*>(&Ws[cur][kk][tr * 8]);
            float4 a1 = *reinterpret_cast<const float4*>(&Ws[cur][kk][tr * 8 + 4]);
            u64t av[8];
            PACK2(av[0], a0.x); PACK2(av[1], a0.y); PACK2(av[2], a0.z); PACK2(av[3], a0.w);
            PACK2(av[4], a1.x); PACK2(av[5], a1.y); PACK2(av[6], a1.z); PACK2(av[7], a1.w);
#pragma unroll
            for (int i = 0; i < 8; i++)
#pragma unroll
                for (int q = 0; q < 4; q++) FMA2(acc[i][q], av[i], xv[q]);
        }
        if (ch < 31) {
            const int nxt = cur ^ 1;
            Ws[nxt][wc40 * 4 + 0][wmm0] = wpre0.x; Ws[nxt][wc40 * 4 + 1][wmm0] = wpre0.y;
            Ws[nxt][wc40 * 4 + 2][wmm0] = wpre0.z; Ws[nxt][wc40 * 4 + 3][wmm0] = wpre0.w;
            Ws[nxt][wc41 * 4 + 0][wmm1] = wpre1.x; Ws[nxt][wc41 * 4 + 1][wmm1] = wpre1.y;
            Ws[nxt][wc41 * 4 + 2][wmm1] = wpre1.z; Ws[nxt][wc41 * 4 + 3][wmm1] = wpre1.w;
#pragma unroll
            for (int r = 0; r < 4; r++)
                *reinterpret_cast<float4*>(&Xs[nxt][xk0 + r * 4][xn0]) = xpre[r];
            __syncthreads();
        }
    }

#pragma unroll
    for (int i = 0; i < 8; i++) {
        int m = m0 + tr * 8 + i;
        float bi = bias[m];
        float* cr = C + (size_t)m * Tc + n0 + tc * 8;
        float o[8];
#pragma unroll
        for (int q = 0; q < 4; q++) UNPACK2(o[2 * q], o[2 * q + 1], acc[i][q]);
        float4 o0 = {o[0] + bi, o[1] + bi, o[2] + bi, o[3] + bi};
        float4 o1 = {o[4] + bi, o[5] + bi, o[6] + bi, o[7] + bi};
        *reinterpret_cast<float4*>(cr)     = o0;
        *reinterpret_cast<float4*>(cr + 4) = o1;
    }
}

// ---------------- fused normalize (shuffle reductions) ----------------------
__global__ void normalize(float* __restrict__ Kd, const float* __restrict__ Qd,
                          const float* __restrict__ Vd,
                          const float* __restrict__ gq, const float* __restrict__ bq,
                          const float* __restrict__ gv, const float* __restrict__ bv,
                          float* __restrict__ qsc, float* __restrict__ qof,
                          float* __restrict__ vsc, float* __restrict__ vof)
{
    const int tid  = threadIdx.x;
    const int lane = tid & 31;
    const int wrp  = tid >> 5;      // 0..7
    __shared__ float r1[8], r2[8];

    if (blockIdx.x < 512) {
        float* r = Kd + (size_t)blockIdx.x * Tc;
        float v[4];
        float m = -1e30f;
#pragma unroll
        for (int j = 0; j < 4; j++) { v[j] = r[tid + j * 256]; m = fmaxf(m, v[j]); }
#pragma unroll
        for (int o = 16; o > 0; o >>= 1) m = fmaxf(m, __shfl_xor_sync(0xffffffffu, m, o));
        if (lane == 0) r1[wrp] = m;
        __syncthreads();
        float M = r1[0];
#pragma unroll
        for (int i = 1; i < 8; i++) M = fmaxf(M, r1[i]);

        float sum = 0.f;
#pragma unroll
        for (int j = 0; j < 4; j++) { v[j] = expf(v[j] - M); sum += v[j]; }
#pragma unroll
        for (int o = 16; o > 0; o >>= 1) sum += __shfl_xor_sync(0xffffffffu, sum, o);
        if (lane == 0) r2[wrp] = sum;
        __syncthreads();
        float S = 0.f;
#pragma unroll
        for (int i = 0; i < 8; i++) S += r2[i];
        float inv = 1.f / S;
#pragma unroll
        for (int j = 0; j < 4; j++) r[tid + j * 256] = v[j] * inv;
        return;
    }

    const float* data;
    const float *gamma, *beta;
    float *osc, *oof;
    int c, C;
    if (blockIdx.x < 576) { c = blockIdx.x - 512; C = Kc; data = Qd; gamma = gq; beta = bq; osc = qsc; oof = qof; }
    else                  { c = blockIdx.x - 576; C = Vc; data = Vd; gamma = gv; beta = bv; osc = vsc; oof = vof; }

    float s = 0.f, sq = 0.f;
    for (int i = tid; i < Bc * Tc; i += 256) {
        int b = i >> 10, t = i & 1023;
        float z = data[((size_t)b * C + c) * Tc + t];
        s += z; sq += z * z;
    }
#pragma unroll
    for (int o = 16; o > 0; o >>= 1) {
        s  += __shfl_xor_sync(0xffffffffu, s, o);
        sq += __shfl_xor_sync(0xffffffffu, sq, o);
    }
    if (lane == 0) { r1[wrp] = s; r2[wrp] = sq; }
    __syncthreads();
    if (tid == 0) {
        float S = 0.f, SQ = 0.f;
#pragma unroll
        for (int i = 0; i < 8; i++) { S += r1[i]; SQ += r2[i]; }
        const float invN = 1.f / (Bc * Tc);
        float mean = S * invN;
        float var  = SQ * invN - mean * mean;
        float g  = gamma[c] * rsqrtf(var + EPSc);
        osc[c] = g;
        oof[c] = beta[c] - mean * g;
    }
}

// ---------------- mid kernel: cl_part (blocks 0..255) + qpos (blocks 256..383)
__global__ void __launch_bounds__(256, 4)
mid_kernel(const float* __restrict__ Kn, const float* __restrict__ Vr,
           float* __restrict__ CLp,
           const float* __restrict__ Qr, const float* __restrict__ pos_w,
           const float* __restrict__ pos_b,
           const float* __restrict__ qsc, const float* __restrict__ qof,
           float* __restrict__ qpos, float* __restrict__ qb)
{
    __shared__ float smem[5728];
    const int tid = threadIdx.x;   // 256

    if (blockIdx.x < 256) {
        const int xid = blockIdx.x;
        const int v0 = (xid & 3) * 64;
        const int b  = (xid >> 2) & 7;
        const int ts = xid >> 5;         // 0..7
        const float* Ab = Kn + (size_t)b * Kc * Tc;
        const float* Vb = Vr + (size_t)b * Vc * Tc;

        float* As = smem;            // [32][65]
        float* Bs = smem + 2080;     // [32][66]

        const int tr = tid >> 4;
        const int tc = tid & 15;

        u64t acc[4][2];
#pragma unroll
        for (int i = 0; i < 4; i++) { acc[i][0] = 0ULL; acc[i][1] = 0ULL; }

        for (int t0 = ts * 128; t0 < ts * 128 + 128; t0 += 32) {
#pragma unroll
            for (int i = tid; i < 64 * 32; i += 256) {
                int r = i >> 5, tt = i & 31;
                As[tt * 65 + r] = Ab[(size_t)r * Tc + t0 + tt];
                Bs[tt * 66 + r] = Vb[(size_t)(v0 + r) * Tc + t0 + tt];
            }
            __syncthreads();
#pragma unroll
            for (int tt = 0; tt < 32; tt++) {
                const float* ar = &As[tt * 65 + tr * 4];
                const u64t* br = reinterpret_cast<const u64t*>(&Bs[tt * 66 + tc * 4]);
                u64t b0 = br[0], b1 = br[1];
                u64t a2[4];
                PACK2(a2[0], ar[0]); PACK2(a2[1], ar[1]);
                PACK2(a2[2], ar[2]); PACK2(a2[3], ar[3]);
#pragma unroll
                for (int i = 0; i < 4; i++) {
                    FMA2(acc[i][0], a2[i], b0);
                    FMA2(acc[i][1], a2[i], b1);
                }
            }
            __syncthreads();
        }
        float* Cb = CLp + (size_t)ts * BKV + (size_t)b * Kc * Vc;
#pragma unroll
        for (int i = 0; i < 4; i++) {
            float o[4];
            UNPACK2(o[0], o[1], acc[i][0]);
            UNPACK2(o[2], o[3], acc[i][1]);
            *reinterpret_cast<float4*>(&Cb[(size_t)(tr * 4 + i) * Vc + v0 + tc * 4]) =
                make_float4(o[0], o[1], o[2], o[3]);
        }
    } else {
        const int idx = blockIdx.x - 256;
        const int t0 = (idx & 15) * 64;
        const int b  = idx >> 4;

        float* Qs  = smem;                      // [64][65]
        float* pws = smem + 64 * 65;            // [64][24]
        float* cs  = smem + 64 * 65 + 64 * 24;  // [24]

        for (int i = tid; i < 64 * 64; i += 256) {
            int k = i >> 6, t = i & 63;
            Qs[k * 65 + t] = Qr[((size_t)b * Kc + k) * Tc + t0 + t];
        }
        for (int i = tid; i < Kc * KSc; i += 256) {
            int k = i / KSc, s = i % KSc;
            pws[k * 24 + s] = qsc[k] * pos_w[k * KSc + s];
        }
        if (tid < Kc) pws[tid * 24 + 23] = qsc[tid] * pos_b[tid];
        if (tid < 24) {
            float c = 0.f;
            if (tid < 23) {
                for (int k = 0; k < Kc; k++) c += qof[k] * pos_w[k * KSc + tid];
            } else {
                for (int k = 0; k < Kc; k++) c += qof[k] * pos_b[k];
            }
            cs[tid] = c;
        }
        __syncthreads();

        const int t  = tid & 63;
        const int sg = tid >> 6;

        float acc[6];
#pragma unroll
        for (int j = 0; j < 6; j++) acc[j] = cs[sg * 6 + j];

#pragma unroll 8
        for (int k = 0; k < Kc; k++) {
            float q = Qs[k * 65 + t];
#pragma unroll
            for (int j = 0; j < 6; j++) acc[j] += q * pws[k * 24 + sg * 6 + j];
        }
#pragma unroll
        for (int j = 0; j < 6; j++) {
            int slot = sg * 6 + j;
            if (slot < 23) qpos[((size_t)b * Tc + t0 + t) * KSc + slot] = acc[j];
            else           qb[(size_t)b * Tc + t0 + t] = acc[j];
        }
    }
}

// CL = vsc[v]*(sum of 8 partials) + vof[v]
__global__ void cl_reduce(const float* __restrict__ CLp, float* __restrict__ CL,
                          const float* __restrict__ vsc, const float* __restrict__ vof)
{
    int i = blockIdx.x * 256 + threadIdx.x;
    int v = i & (Vc - 1);
    float s = 0.f;
#pragma unroll
    for (int p = 0; p < NSPLIT; p++) s += CLp[i + (size_t)p * BKV];
    CL[i] = s * vsc[v] + vof[v];
}

// ---------------- fused output: v-block 64, dynamic smem, packed f32x2 -------
__global__ void out_kernel(const float* __restrict__ Qr, const float* __restrict__ CL,
                           const float* __restrict__ Vr, const float* __restrict__ qpos,
                           const float* __restrict__ qb,
                           const float* __restrict__ qsc, const float* __restrict__ qof,
                           const float* __restrict__ vsc, const float* __restrict__ vof,
                           float* __restrict__ out)
{
    extern __shared__ float dsm[];
    float* Qs  = dsm;              // [64][64]
    float* cls = dsm + 4096;       // [64][64]
    float* qps = dsm + 8192;       // [64][25]
    float* Vs  = dsm + 9792;       // [86][70]
    float* qsS = dsm + 15812;
    float* qoS = dsm + 15876;
    float* vsS = dsm + 15940;
    float* voS = dsm + 16004;

    const int b  = blockIdx.z;
    const int v0 = blockIdx.y * 64;
    const int t0 = blockIdx.x * 64;
    const int tid = threadIdx.x;
    const int tl = tid & 63;
    const int vlane = tid >> 6;

    if (tid < 64)        { qsS[tid] = qsc[tid]; qoS[tid] = qof[tid]; }
    else if (tid < 128)  { vsS[tid - 64] = vsc[v0 + tid - 64]; }
    else if (tid < 192)  { voS[tid - 128] = vof[v0 + tid - 128]; }
    __syncthreads();

#pragma unroll 4
    for (int i = tid; i < 64 * 64; i += 256) {
        int k = i >> 6, t = i & 63;
        Qs[k * 64 + t] = Qr[((size_t)b * Kc + k) * Tc + t0 + t] * qsS[k] + qoS[k];
    }
#pragma unroll 4
    for (int i = tid; i < 64 * 64; i += 256) {
        int k = i >> 6, vv = i & 63;
        cls[k * 64 + vv] = CL[((size_t)b * Kc + k) * Vc + v0 + vv];
    }
    for (int i = tid; i < 64 * KSc; i += 256) {
        int t = i / KSc, s = i % KSc;
        qps[t * 25 + s] = qpos[((size_t)b * Tc + t0 + t) * KSc + s];
    }
    if (tid < 64) qps[tid * 25 + 23] = qb[b * Tc + t0 + tid];
#pragma unroll 4
    for (int i = tid; i < 64 * 86; i += 256) {
        int vv = i / 86, idx = i % 86;
        int tg = t0 - 11 + idx;
        Vs[idx * 70 + vv] = (tg >= 0 && tg < Tc)
                                ? Vr[((size_t)b * Vc + v0 + vv) * Tc + tg] * vsS[vv] + voS[vv]
                                : 0.f;
    }
    __syncthreads();

    u64t accp[8];
#pragma unroll
    for (int q = 0; q < 8; q++) accp[q] = 0ULL;

#pragma unroll
    for (int k = 0; k < Kc; k++) {
        u64t qv;
        PACK2(qv, Qs[k * 64 + tl]);
        const u64t* cp = reinterpret_cast<const u64t*>(&cls[k * 64 + vlane * 16]);
#pragma unroll
        for (int q = 0; q < 8; q++) FMA2(accp[q], qv, cp[q]);
    }

#pragma unroll
    for (int s = 0; s < KSc; s++) {
        u64t qd;
        PACK2(qd, qps[tl * 25 + s]);
        const u64t* vp = reinterpret_cast<const u64t*>(&Vs[(tl + s) * 70 + vlane * 16]);
#pragma unroll
        for (int q = 0; q < 8; q++) FMA2(accp[q], qd, vp[q]);
    }

    float qbv = qps[tl * 25 + 23];
#pragma unroll
    for (int q = 0; q < 8; q++) {
        float lo, hi;
        UNPACK2(lo, hi, accp[q]);
        int v = v0 + vlane * 16 + 2 * q;
        out[((size_t)b * Vc + v) * Tc + t0 + tl]     = lo + qbv;
        out[((size_t)b * Vc + v + 1) * Tc + t0 + tl] = hi + qbv;
    }
}

// ---------------- launch ----------------
extern "C" void kernel_launch(void* const* d_in, const int* in_sizes, int n_in,
                              void* d_out, int out_size)
{
    const float* x       = (const float*)d_in[0];
    const float* context = (const float*)d_in[1];
    const float* Wq      = (const float*)d_in[2];
    const float* bq      = (const float*)d_in[3];
    const float* Wk      = (const float*)d_in[4];
    const float* bk      = (const float*)d_in[5];
    const float* Wv      = (const float*)d_in[6];
    const float* bv      = (const float*)d_in[7];
    const float* gamma_q = (const float*)d_in[8];
    const float* beta_q  = (const float*)d_in[9];
    const float* gamma_v = (const float*)d_in[10];
    const float* beta_v  = (const float*)d_in[11];
    const float* pos_w   = (const float*)d_in[12];
    const float* pos_b   = (const float*)d_in[13];
    float* out = (float*)d_out;

    float *dQ, *dK, *dV, *dCLp, *dCL, *dqp, *dqb, *dqsc, *dqof, *dvsc, *dvof;
    cudaGetSymbolAddress((void**)&dQ,   g_Q);
    cudaGetSymbolAddress((void**)&dK,   g_K);
    cudaGetSymbolAddress((void**)&dV,   g_V);
    cudaGetSymbolAddress((void**)&dCLp, g_CLp);
    cudaGetSymbolAddress((void**)&dCL,  g_CL);
    cudaGetSymbolAddress((void**)&dqp,  g_qpos);
    cudaGetSymbolAddress((void**)&dqb,  g_qb);
    cudaGetSymbolAddress((void**)&dqsc, g_qsc);
    cudaGetSymbolAddress((void**)&dqof, g_qof);
    cudaGetSymbolAddress((void**)&dvsc, g_vsc);
    cudaGetSymbolAddress((void**)&dvof, g_vof);

    const int OUT_SMEM = 16068 * 4;
    cudaFuncSetAttribute(out_kernel, cudaFuncAttributeMaxDynamicSharedMemorySize, OUT_SMEM);

    proj_all<<<dim3(Tc / 128, 1, 48), 128>>>(x, context, Wq, bq, Wk, bk, Wv, bv, dQ, dK, dV);
    normalize<<<832, 256>>>(dK, dQ, dV, gamma_q, beta_q, gamma_v, beta_v,
                            dqsc, dqof, dvsc, dvof);
    mid_kernel<<<384, 256>>>(dK, dV, dCLp, dQ, pos_w, pos_b, dqsc, dqof, dqp, dqb);
    cl_reduce<<<BKV / 256, 256>>>(dCLp, dCL, dvsc, dvof);
    out_kernel<<<dim3(Tc / 64, Vc / 64, Bc), 256, OUT_SMEM>>>(dQ, dCL, dV, dqp, dqb,
                                                              dqsc, dqof, dvsc, dvof, out);
}